// round 2
// baseline (speedup 1.0000x reference)
#include <cuda_runtime.h>
#include <cstdint>

// PointerNet_30949534335591
//
// Mathematical reduction: ptr_W has shape (1, H), so the decoder's
// logits = h @ ptr_W.T + ptr_b is [B, 1]; argmax over axis=1 of a
// single-column tensor is identically 0 for every row and every of the
// S decoder steps ("always 0, faithful to source" per the reference
// comment). The output ptrs.T is therefore a constant zeros tensor of
// shape [B, S] = [256, 512], independent of all 11 inputs. The
// encoder/decoder LSTM scans are dead code w.r.t. the observable
// output.
//
// Optimal kernel: write out_size int32 zeros (d_out is poisoned to
// 0xAA by the harness, so the stores are required). 512 KB of stores,
// one 128-bit store per thread, single wave.

__global__ void __launch_bounds__(256, 1)
pointer_net_zero_kernel(int4* __restrict__ out4, int n4, int* __restrict__ out, int n) {
    int i = blockIdx.x * blockDim.x + threadIdx.x;
    if (i < n4) {
        out4[i] = make_int4(0, 0, 0, 0);
    }
    // Defensive scalar tail for n not divisible by 4 (n = 131072 is;
    // this predicate is false for every thread in practice).
    int t = (n4 << 2) + i;
    if (t < n) {
        out[t] = 0;
    }
}

extern "C" void kernel_launch(void* const* d_in, const int* in_sizes, int n_in,
                              void* d_out, int out_size) {
    (void)d_in; (void)in_sizes; (void)n_in;
    const int threads = 256;
    int n4 = out_size >> 2;                      // 32768 int4 stores
    int blocks = (n4 + threads - 1) / threads;   // 128 blocks
    if (blocks < 1) blocks = 1;
    pointer_net_zero_kernel<<<blocks, threads>>>(
        (int4*)d_out, n4, (int*)d_out, out_size);
}